// round 2
// baseline (speedup 1.0000x reference)
#include <cuda_runtime.h>

#define TSEQ 2048
#define CH   2048
#define NH   16
#define HD   128

// Scratch (allocation-free rule: __device__ globals)
__device__ float g_q[TSEQ * CH];
__device__ float g_k[TSEQ * CH];
__device__ float g_v[TSEQ * CH];
__device__ float g_o[TSEQ * CH];

// ---------------------------------------------------------------------------
// C[M,N] = A[M,K] @ B[N,K]^T   (M = N = K = 2048, row-major)
// 128x128 block tile, BK=16, 256 threads, 8x8 micro-tile (split quadrants)
// ---------------------------------------------------------------------------
__global__ __launch_bounds__(256) void sgemm_tn(const float* __restrict__ A,
                                                const float* __restrict__ B,
                                                float* __restrict__ C) {
    __shared__ float As[16][129];
    __shared__ float Bs[16][129];

    const int tid = threadIdx.x;
    const int tx = tid & 15;
    const int ty = tid >> 4;
    const int m0 = blockIdx.y * 128;
    const int n0 = blockIdx.x * 128;

    float acc[8][8];
#pragma unroll
    for (int i = 0; i < 8; i++)
#pragma unroll
        for (int j = 0; j < 8; j++) acc[i][j] = 0.f;

    for (int k0 = 0; k0 < CH; k0 += 16) {
#pragma unroll
        for (int l = 0; l < 2; l++) {
            int u   = tid + l * 256;
            int row = u >> 2;
            int c4  = (u & 3) * 4;
            float4 va = *(const float4*)(A + (size_t)(m0 + row) * CH + k0 + c4);
            As[c4 + 0][row] = va.x;
            As[c4 + 1][row] = va.y;
            As[c4 + 2][row] = va.z;
            As[c4 + 3][row] = va.w;
            float4 vb = *(const float4*)(B + (size_t)(n0 + row) * CH + k0 + c4);
            Bs[c4 + 0][row] = vb.x;
            Bs[c4 + 1][row] = vb.y;
            Bs[c4 + 2][row] = vb.z;
            Bs[c4 + 3][row] = vb.w;
        }
        __syncthreads();

#pragma unroll
        for (int kk = 0; kk < 16; kk++) {
            float a[8], b[8];
#pragma unroll
            for (int i = 0; i < 4; i++) {
                a[i]     = As[kk][ty * 4 + i];
                a[i + 4] = As[kk][64 + ty * 4 + i];
                b[i]     = Bs[kk][tx * 4 + i];
                b[i + 4] = Bs[kk][64 + tx * 4 + i];
            }
#pragma unroll
            for (int i = 0; i < 8; i++)
#pragma unroll
                for (int j = 0; j < 8; j++) acc[i][j] += a[i] * b[j];
        }
        __syncthreads();
    }

#pragma unroll
    for (int i = 0; i < 8; i++) {
        int m = m0 + ((i < 4) ? (ty * 4 + i) : (64 + ty * 4 + i - 4));
#pragma unroll
        for (int j = 0; j < 8; j++) {
            int n = n0 + ((j < 4) ? (tx * 4 + j) : (64 + tx * 4 + j - 4));
            C[(size_t)m * CH + n] = acc[i][j];
        }
    }
}

// ---------------------------------------------------------------------------
// ReBased feature map: y = LayerNorm(x * gamma + beta) over D=128 per (t,h)
// row, with optional D^-0.5 scale (for q). One warp per row.
// blockIdx.y == 0 -> g_q (scaled), == 1 -> g_k
// ---------------------------------------------------------------------------
__global__ __launch_bounds__(256) void featmap(const float* __restrict__ gamma,
                                               const float* __restrict__ beta) {
    const int warp = threadIdx.x >> 5;
    const int lane = threadIdx.x & 31;
    const int row  = blockIdx.x * 8 + warp;   // 0 .. T*NH-1
    float* base = (blockIdx.y == 0) ? g_q : g_k;
    const float scale = (blockIdx.y == 0) ? 0.08838834764831845f : 1.0f;  // D^-0.5
    const int t = row >> 4;
    const int h = row & 15;
    float* p = base + (size_t)t * CH + h * HD;

    float x[4];
    float s = 0.f, sq = 0.f;
#pragma unroll
    for (int r = 0; r < 4; r++) {
        int d = lane + 32 * r;
        float y = p[d] * gamma[d] + beta[d];
        x[r] = y;
        s  += y;
        sq += y * y;
    }
#pragma unroll
    for (int o = 16; o; o >>= 1) {
        s  += __shfl_xor_sync(0xFFFFFFFFu, s, o);
        sq += __shfl_xor_sync(0xFFFFFFFFu, sq, o);
    }
    const float mu  = s * (1.0f / HD);
    const float var = sq * (1.0f / HD) - mu * mu;
    const float rs  = rsqrtf(var + 1e-5f) * scale;
#pragma unroll
    for (int r = 0; r < 4; r++) p[lane + 32 * r] = (x[r] - mu) * rs;
}

// ---------------------------------------------------------------------------
// Causal quadratic attention (no softmax):
//   S = (q . k)^2 (causal), O = S @ v, z = rowsum(S), out = O / (z + 1e-5)
// One block per (q-tile of 64 rows, head). Streams k/v tiles; S never hits
// global memory.
// smem: qs/ks/vs 64x129, s2 64x65, z 64  -> 115968 bytes dynamic
// ---------------------------------------------------------------------------
__global__ __launch_bounds__(256) void rebased_attn() {
    extern __shared__ float sm[];
    float* qs  = sm;                     // 64*129
    float* ks  = qs + 64 * 129;          // 64*129
    float* vs  = ks + 64 * 129;          // 64*129
    float* s2  = vs + 64 * 129;          // 64*65
    float* zsh = s2 + 64 * 65;           // 64

    const int tid = threadIdx.x;
    const int tx = tid & 15;
    const int ty = tid >> 4;
    const int qt = blockIdx.x;           // 0..31
    const int h  = blockIdx.y;           // 0..15
    const int q0 = qt * 64;

    // load q tile (64 x 128)
#pragma unroll
    for (int it = 0; it < 8; it++) {
        int u   = tid + it * 256;
        int row = u >> 5;
        int c4  = (u & 31) * 4;
        float4 v4 = *(const float4*)(g_q + (size_t)(q0 + row) * CH + h * HD + c4);
        qs[row * 129 + c4 + 0] = v4.x;
        qs[row * 129 + c4 + 1] = v4.y;
        qs[row * 129 + c4 + 2] = v4.z;
        qs[row * 129 + c4 + 3] = v4.w;
    }
    if (tid < 64) zsh[tid] = 0.f;

    float o[4][8];
#pragma unroll
    for (int i = 0; i < 4; i++)
#pragma unroll
        for (int c = 0; c < 8; c++) o[i][c] = 0.f;

    for (int kt = 0; kt <= qt; kt++) {
        const int k0 = kt * 64;
        __syncthreads();  // ks/vs/s2 free from previous iter; q load visible

#pragma unroll
        for (int it = 0; it < 8; it++) {
            int u   = tid + it * 256;
            int row = u >> 5;
            int c4  = (u & 31) * 4;
            float4 vk = *(const float4*)(g_k + (size_t)(k0 + row) * CH + h * HD + c4);
            ks[row * 129 + c4 + 0] = vk.x;
            ks[row * 129 + c4 + 1] = vk.y;
            ks[row * 129 + c4 + 2] = vk.z;
            ks[row * 129 + c4 + 3] = vk.w;
            float4 vv = *(const float4*)(g_v + (size_t)(k0 + row) * CH + h * HD + c4);
            vs[row * 129 + c4 + 0] = vv.x;
            vs[row * 129 + c4 + 1] = vv.y;
            vs[row * 129 + c4 + 2] = vv.z;
            vs[row * 129 + c4 + 3] = vv.w;
        }
        __syncthreads();

        // S = q . k^T  (64x64, 4x4 per thread)
        float acc[4][4];
#pragma unroll
        for (int i = 0; i < 4; i++)
#pragma unroll
            for (int j = 0; j < 4; j++) acc[i][j] = 0.f;

#pragma unroll 4
        for (int d = 0; d < 128; d++) {
            float a[4], b[4];
#pragma unroll
            for (int i = 0; i < 4; i++) a[i] = qs[(ty * 4 + i) * 129 + d];
#pragma unroll
            for (int j = 0; j < 4; j++) b[j] = ks[(tx * 4 + j) * 129 + d];
#pragma unroll
            for (int i = 0; i < 4; i++)
#pragma unroll
                for (int j = 0; j < 4; j++) acc[i][j] += a[i] * b[j];
        }

        // square, causal mask (diagonal tile only), z partial, store S^2
        const bool diag = (kt == qt);
        float zp[4] = {0.f, 0.f, 0.f, 0.f};
#pragma unroll
        for (int i = 0; i < 4; i++) {
            int li = ty * 4 + i;
#pragma unroll
            for (int j = 0; j < 4; j++) {
                int lj = tx * 4 + j;
                float sv = acc[i][j];
                sv = sv * sv;
                if (diag && lj > li) sv = 0.f;
                s2[li * 65 + lj] = sv;
                zp[i] += sv;
            }
        }
#pragma unroll
        for (int i = 0; i < 4; i++) atomicAdd(&zsh[ty * 4 + i], zp[i]);
        __syncthreads();

        // O += S^2 @ V   (64x128, 4 rows x 8 cols per thread, split cols)
        for (int j = 0; j < 64; j++) {
            float sv[4];
#pragma unroll
            for (int i = 0; i < 4; i++) sv[i] = s2[(ty * 4 + i) * 65 + j];
            float vv[8];
#pragma unroll
            for (int c = 0; c < 4; c++) {
                vv[c]     = vs[j * 129 + tx * 4 + c];
                vv[c + 4] = vs[j * 129 + 64 + tx * 4 + c];
            }
#pragma unroll
            for (int i = 0; i < 4; i++)
#pragma unroll
                for (int c = 0; c < 8; c++) o[i][c] += sv[i] * vv[c];
        }
    }
    __syncthreads();

    // divide by (z + EPS) and store
#pragma unroll
    for (int i = 0; i < 4; i++) {
        int li = ty * 4 + i;
        float inv = 1.0f / (zsh[li] + 1e-5f);
        float* op = g_o + (size_t)(q0 + li) * CH + h * HD;
#pragma unroll
        for (int c = 0; c < 4; c++) {
            op[tx * 4 + c]      = o[i][c] * inv;
            op[64 + tx * 4 + c] = o[i][c + 4] * inv;
        }
    }
}

// ---------------------------------------------------------------------------
extern "C" void kernel_launch(void* const* d_in, const int* in_sizes, int n_in,
                              void* d_out, int out_size) {
    const float* X     = (const float*)d_in[0];
    const float* Wq    = (const float*)d_in[1];
    const float* Wk    = (const float*)d_in[2];
    const float* Wv    = (const float*)d_in[3];
    const float* Wo    = (const float*)d_in[4];
    const float* gamma = (const float*)d_in[5];
    const float* beta  = (const float*)d_in[6];
    float* out = (float*)d_out;

    float *q, *k, *v, *o;
    cudaGetSymbolAddress((void**)&q, g_q);
    cudaGetSymbolAddress((void**)&k, g_k);
    cudaGetSymbolAddress((void**)&v, g_v);
    cudaGetSymbolAddress((void**)&o, g_o);

    const int ATTN_SMEM = (3 * 64 * 129 + 64 * 65 + 64) * (int)sizeof(float);
    cudaFuncSetAttribute(rebased_attn,
                         cudaFuncAttributeMaxDynamicSharedMemorySize, ATTN_SMEM);

    dim3 gGemm(16, 16), b256(256);

    // Q/K/V projections
    sgemm_tn<<<gGemm, b256>>>(X, Wq, q);
    sgemm_tn<<<gGemm, b256>>>(X, Wk, k);
    sgemm_tn<<<gGemm, b256>>>(X, Wv, v);

    // feature map (q scaled by D^-0.5, k unscaled)
    featmap<<<dim3(TSEQ * NH / 8, 2), b256>>>(gamma, beta);

    // causal quadratic attention
    rebased_attn<<<dim3(TSEQ / 64, NH), b256, ATTN_SMEM>>>();

    // output projection
    sgemm_tn<<<gGemm, b256>>>(o, Wo, out);
}